// round 10
// baseline (speedup 1.0000x reference)
#include <cuda_runtime.h>
#include <cuda_bf16.h>
#include <math.h>

// Problem-fixed maxima (shapes are fixed by the dataset)
#define NMAX      65536
#define NODESMAX  100000

// ---- scratch (device globals; no dynamic allocation allowed) ----
__device__ float g_qkvs[(size_t)NMAX * 512];   // per node: q[128] | k[128] | v[128] | skip[128]
__device__ float g_agg [(size_t)NMAX * 128];   // unnormalized attention numerator
__device__ float g_den [NMAX * 2];             // per-head softmax denominator
__device__ float g_lu  [NMAX];                 // last_update gathered to local rows
__device__ int   g_assoc[NODESMAX];            // global node id -> local row
__device__ float g_h   [(size_t)NMAX * 64];    // MLP output per node

typedef unsigned long long ull;

// ---- packed f32x2 helpers (sm_103a FFMA2 path) ----
__device__ __forceinline__ ull pack2(float lo, float hi) {
    ull r;
    asm("mov.b64 %0, {%1, %2};" : "=l"(r)
        : "r"(__float_as_uint(lo)), "r"(__float_as_uint(hi)));
    return r;
}
__device__ __forceinline__ void unpack2(ull v, float &lo, float &hi) {
    unsigned int a, b;
    asm("mov.b64 {%0, %1}, %2;" : "=r"(a), "=r"(b) : "l"(v));
    lo = __uint_as_float(a);
    hi = __uint_as_float(b);
}
__device__ __forceinline__ ull fma2(ull a, ull b, ull c) {
    ull d;
    asm("fma.rn.f32x2 %0, %1, %2, %3;" : "=l"(d) : "l"(a), "l"(b), "l"(c));
    return d;
}
__device__ __forceinline__ void red4(float* p, float x, float y, float z, float w) {
    asm volatile("red.global.add.v4.f32 [%0], {%1, %2, %3, %4};"
                 :: "l"(p), "f"(x), "f"(y), "f"(z), "f"(w) : "memory");
}

// ============================================================================
// K0: zero accumulators, reset assoc
// ============================================================================
__global__ void k_init(int Nn, int numNodes) {
    int i = blockIdx.x * 256 + threadIdx.x;
    int aggN = Nn * 128;
    if (i < aggN)      g_agg[i] = 0.f;
    if (i < Nn * 2)    g_den[i] = 0.f;
    if (i < numNodes)  g_assoc[i] = 0;
}

// ============================================================================
// K1: scatter assoc + gather last_update
// ============================================================================
__global__ void k_scatter(const int* __restrict__ n_id,
                          const float* __restrict__ last_update, int Nn) {
    int i = blockIdx.x * 256 + threadIdx.x;
    if (i < Nn) {
        int g = n_id[i];
        g_assoc[g] = i;
        g_lu[i] = last_update[g];
    }
}

// ============================================================================
// K2: node GEMM.  C[N,512] = z[N,256] @ [Wq|Wk|Wv|Wskip] + bias
//     BM=128, BN=128 (one weight matrix per blockIdx.x), BK=16,
//     128 threads, 8x16 micro-tile (compute-bound vs LDS).
//     k0 loop forced rolled (#pragma unroll 1) to bound ptxas input size.
// ============================================================================
__global__ __launch_bounds__(128) void k_node_gemm(
    const int*   __restrict__ n_id,
    const float* __restrict__ memory, const float* __restrict__ pos_memory,
    const float* __restrict__ Wq, const float* __restrict__ Wk,
    const float* __restrict__ Wv, const float* __restrict__ Ws,
    const float* __restrict__ bq, const float* __restrict__ bk,
    const float* __restrict__ bv, const float* __restrict__ bs)
{
    __shared__ __align__(16) float As[16][128];
    __shared__ __align__(16) float Bs[16][128];

    const float* W; const float* bias;
    int bx = blockIdx.x;
    if      (bx == 0) { W = Wq; bias = bq; }
    else if (bx == 1) { W = Wk; bias = bk; }
    else if (bx == 2) { W = Wv; bias = bv; }
    else              { W = Ws; bias = bs; }

    int tid = threadIdx.x;
    int tx = tid & 7;          // col group: cols tx*16 .. +15
    int ty = tid >> 3;         // row group: rows ty*8 .. +7
    int row0 = blockIdx.y << 7;

    int nid  = n_id[row0 + tid];   // A-load: this thread's row
    int brow = tid >> 3;           // B-load row (0..15)
    int bcol = (tid & 7) << 4;     // B-load col base

    ull acc[8][8];
#pragma unroll
    for (int i = 0; i < 8; i++)
#pragma unroll
        for (int j = 0; j < 8; j++) acc[i][j] = 0ULL;

#pragma unroll 1
    for (int k0 = 0; k0 < 256; k0 += 16) {
        const float* srcm = (k0 < 128) ? memory : pos_memory;
        int kb = k0 & 127;
        float4 a[4], b[4];
#pragma unroll
        for (int i = 0; i < 4; i++)
            a[i] = __ldg((const float4*)(srcm + (size_t)nid * 128 + kb + 4 * i));
#pragma unroll
        for (int i = 0; i < 4; i++)
            b[i] = __ldg((const float4*)(W + (size_t)(k0 + brow) * 128 + bcol + 4 * i));
        __syncthreads();
#pragma unroll
        for (int i = 0; i < 4; i++) {
            As[4 * i + 0][tid] = a[i].x; As[4 * i + 1][tid] = a[i].y;
            As[4 * i + 2][tid] = a[i].z; As[4 * i + 3][tid] = a[i].w;
        }
#pragma unroll
        for (int i = 0; i < 4; i++)
            *(float4*)&Bs[brow][bcol + 4 * i] = b[i];
        __syncthreads();
#pragma unroll
        for (int kk = 0; kk < 16; kk++) {
            float av[8];
            *(float4*)&av[0] = *(const float4*)&As[kk][ty * 8];
            *(float4*)&av[4] = *(const float4*)&As[kk][ty * 8 + 4];
            ull bv8[8];
            const ull* bp = (const ull*)&Bs[kk][tx * 16];
#pragma unroll
            for (int j = 0; j < 8; j++) bv8[j] = bp[j];
#pragma unroll
            for (int i = 0; i < 8; i++) {
                ull ad = pack2(av[i], av[i]);
#pragma unroll
                for (int j = 0; j < 8; j++)
                    acc[i][j] = fma2(ad, bv8[j], acc[i][j]);
            }
        }
    }

    float bb[16];
#pragma unroll
    for (int i = 0; i < 4; i++)
        *(float4*)&bb[4 * i] = __ldg((const float4*)(bias + tx * 16 + 4 * i));
#pragma unroll
    for (int i = 0; i < 8; i++) {
        int r = row0 + ty * 8 + i;
        float v[16];
#pragma unroll
        for (int j = 0; j < 8; j++) {
            float lo, hi; unpack2(acc[i][j], lo, hi);
            v[2 * j]     = lo + bb[2 * j];
            v[2 * j + 1] = hi + bb[2 * j + 1];
        }
        float* orow = g_qkvs + (size_t)r * 512 + (bx << 7) + tx * 16;
#pragma unroll
        for (int j = 0; j < 4; j++)
            *(float4*)&orow[4 * j] = *(float4*)&v[4 * j];
    }
}

// ============================================================================
// K3: fused edge kernel.  BM=128 edges, BN=128, 128 threads, 8x16 micro.
//   - build edge_attr tile [128 x 16] on the fly (cos time-enc cols 0-63, msg)
//   - GEMM vs We (staged in smem), e stays in registers
//   - epilogue: 8 lanes per edge (16 cols each); score via shfl over 4-lane
//     head groups; ex = exp(score/8); red.global.add.v4 accumulation.
//   k0 loop forced rolled to bound ptxas input size.
// ============================================================================
__global__ __launch_bounds__(128) void k_edge(
    const int*   __restrict__ edge_index, const float* __restrict__ edge_t,
    const float* __restrict__ edge_msg,   const float* __restrict__ We,
    const float* __restrict__ be,         const float* __restrict__ time_w,
    const float* __restrict__ time_b,     int E)
{
    __shared__ int   s_se[128], s_de[128];
    __shared__ float s_tw[64], s_tb[64];
    __shared__ __align__(16) float As[16][128];
    __shared__ __align__(16) float Bs[16][128];

    int tid = threadIdx.x;
    int e0 = blockIdx.x << 7;
    int e  = e0 + tid;
    int ec = (e < E) ? e : (E - 1);
    int my_se = edge_index[ec];
    s_se[tid] = my_se;
    s_de[tid] = edge_index[E + ec];
    float my_rel = g_lu[my_se] - edge_t[ec];
    if (tid < 64) { s_tw[tid] = time_w[tid]; s_tb[tid] = time_b[tid]; }
    __syncthreads();

    int tx = tid & 7;    // cols tx*16 .. +15 ; head = tx>>2
    int ty = tid >> 3;   // edges ty*8 .. +7
    int brow = tid >> 3;
    int bcol = (tid & 7) << 4;

    ull acc[8][8];
#pragma unroll
    for (int i = 0; i < 8; i++)
#pragma unroll
        for (int j = 0; j < 8; j++) acc[i][j] = 0ULL;

#pragma unroll 1
    for (int k0 = 0; k0 < 128; k0 += 16) {
        float av[16];
        if (k0 < 64) {
#pragma unroll
            for (int ii = 0; ii < 16; ii++) {
                int c = k0 + ii;
                av[ii] = cosf(my_rel * s_tw[c] + s_tb[c]);
            }
        } else {
#pragma unroll
            for (int ii = 0; ii < 4; ii++) {
                float4 m = __ldg((const float4*)(edge_msg + (size_t)ec * 64 + (k0 - 64) + 4 * ii));
                av[4 * ii + 0] = m.x; av[4 * ii + 1] = m.y;
                av[4 * ii + 2] = m.z; av[4 * ii + 3] = m.w;
            }
        }
        float4 b[4];
#pragma unroll
        for (int i = 0; i < 4; i++)
            b[i] = __ldg((const float4*)(We + (size_t)(k0 + brow) * 128 + bcol + 4 * i));
        __syncthreads();
#pragma unroll
        for (int ii = 0; ii < 16; ii++) As[ii][tid] = av[ii];
#pragma unroll
        for (int i = 0; i < 4; i++)
            *(float4*)&Bs[brow][bcol + 4 * i] = b[i];
        __syncthreads();
#pragma unroll
        for (int kk = 0; kk < 16; kk++) {
            float a8[8];
            *(float4*)&a8[0] = *(const float4*)&As[kk][ty * 8];
            *(float4*)&a8[4] = *(const float4*)&As[kk][ty * 8 + 4];
            ull bv8[8];
            const ull* bp = (const ull*)&Bs[kk][tx * 16];
#pragma unroll
            for (int j = 0; j < 8; j++) bv8[j] = bp[j];
#pragma unroll
            for (int i = 0; i < 8; i++) {
                ull ad = pack2(a8[i], a8[i]);
#pragma unroll
                for (int j = 0; j < 8; j++)
                    acc[i][j] = fma2(ad, bv8[j], acc[i][j]);
            }
        }
    }

    float beb[16];
#pragma unroll
    for (int i = 0; i < 4; i++)
        *(float4*)&beb[4 * i] = __ldg((const float4*)(be + tx * 16 + 4 * i));

    // epilogue: 8 lanes (same ty, tx 0-7) share an edge; tx 0-3 head0, 4-7 head1
#pragma unroll 1
    for (int i = 0; i < 8; i++) {
        int el = ty * 8 + i;
        int de = s_de[el], se = s_se[el];
        float evv[16];
#pragma unroll
        for (int j = 0; j < 8; j++) {
            float lo, hi; unpack2(acc[i][j], lo, hi);
            evv[2 * j]     = lo + beb[2 * j];
            evv[2 * j + 1] = hi + beb[2 * j + 1];
        }
        const float* qp = g_qkvs + (size_t)de * 512 + tx * 16;
        const float* kp = g_qkvs + (size_t)se * 512 + 128 + tx * 16;
        float s = 0.f;
#pragma unroll
        for (int j = 0; j < 4; j++) {
            float4 q4 = __ldg((const float4*)(qp + 4 * j));
            float4 k4 = __ldg((const float4*)(kp + 4 * j));
            s += q4.x * (k4.x + evv[4 * j + 0]) + q4.y * (k4.y + evv[4 * j + 1])
               + q4.z * (k4.z + evv[4 * j + 2]) + q4.w * (k4.w + evv[4 * j + 3]);
        }
        s += __shfl_xor_sync(0xffffffffu, s, 1);
        s += __shfl_xor_sync(0xffffffffu, s, 2);
        float ex = expf(s * 0.125f);   // / sqrt(HD=64)

        if (e0 + el < E) {
            const float* vp = g_qkvs + (size_t)se * 512 + 256 + tx * 16;
            float* dst = g_agg + (size_t)de * 128 + tx * 16;
#pragma unroll
            for (int j = 0; j < 4; j++) {
                float4 v4 = __ldg((const float4*)(vp + 4 * j));
                red4(dst + 4 * j,
                     ex * (v4.x + evv[4 * j + 0]), ex * (v4.y + evv[4 * j + 1]),
                     ex * (v4.z + evv[4 * j + 2]), ex * (v4.w + evv[4 * j + 3]));
            }
            if      (tx == 0) atomicAdd(&g_den[de * 2 + 0], ex);
            else if (tx == 4) atomicAdd(&g_den[de * 2 + 1], ex);
        }
    }
}

// ============================================================================
// K4: per-node normalize + skip + MLP -> g_h[N,64].  64 nodes per block.
// ============================================================================
__global__ __launch_bounds__(256) void k_node_final(
    const float* __restrict__ mlp_w, const float* __restrict__ mlp_b)
{
    __shared__ float so[64][129];
    __shared__ __align__(16) float sw[16][64];
    int t = threadIdx.x;
    int base = blockIdx.x << 6;

    // stage normalized+skip node features [64 x 128]
#pragma unroll 1
    for (int r = 0; r < 32; r++) {
        int idx = r * 256 + t;
        int nl = idx >> 7, c = idx & 127;
        int node = base + nl;
        float d = g_den[node * 2 + (c >> 6)];
        so[nl][c] = g_agg[(size_t)node * 128 + c] / (d + 1e-16f)
                  + g_qkvs[(size_t)node * 512 + 384 + c];
    }

    int node = t >> 2;           // 0..63
    int col0 = (t & 3) << 4;     // 0,16,32,48
    ull accs[8];
#pragma unroll
    for (int j = 0; j < 8; j++) accs[j] = 0ULL;

#pragma unroll 1
    for (int d0 = 0; d0 < 128; d0 += 16) {
        __syncthreads();
        // load mlp_w chunk [16 x 64]
        {
            int wr = t >> 4, wc = (t & 15) << 2;
            *(float4*)&sw[wr][wc] = __ldg((const float4*)(mlp_w + (size_t)(d0 + wr) * 64 + wc));
        }
        __syncthreads();
#pragma unroll
        for (int d = 0; d < 16; d++) {
            float a0 = so[node][d0 + d];
            ull ad = pack2(a0, a0);
            const ull* wp = (const ull*)&sw[d][col0];
#pragma unroll
            for (int j = 0; j < 8; j++) accs[j] = fma2(ad, wp[j], accs[j]);
        }
    }

    float outv[16];
#pragma unroll
    for (int j = 0; j < 8; j++) {
        float lo, hi; unpack2(accs[j], lo, hi);
        outv[2 * j]     = lo + __ldg(mlp_b + col0 + 2 * j);
        outv[2 * j + 1] = hi + __ldg(mlp_b + col0 + 2 * j + 1);
    }
    float* op = g_h + (size_t)(base + node) * 64 + col0;
#pragma unroll
    for (int j = 0; j < 4; j++)
        *(float4*)&op[4 * j] = *(float4*)&outv[4 * j];
}

// ============================================================================
// K5: link predictor.  blocks [0,B) -> pos (src,dst); [B,2B) -> neg (src,neg_dst)
// ============================================================================
__global__ __launch_bounds__(64) void k_link_pred(
    const int* __restrict__ src, const int* __restrict__ dst,
    const int* __restrict__ neg_dst,
    const float* __restrict__ lps_w, const float* __restrict__ lps_b,
    const float* __restrict__ lpd_w, const float* __restrict__ lpd_b,
    const float* __restrict__ lpf_w, const float* __restrict__ lpf_b,
    float* __restrict__ out, int Bn)
{
    __shared__ float sa[64], sb[64];
    __shared__ float red[2];
    int b = blockIdx.x;
    int t = threadIdx.x;
    int pos = (b < Bn);
    int bb = pos ? b : b - Bn;
    int sn = g_assoc[src[bb]];
    int dn = g_assoc[pos ? dst[bb] : neg_dst[bb]];
    sa[t] = g_h[(size_t)sn * 64 + t];
    sb[t] = g_h[(size_t)dn * 64 + t];
    __syncthreads();
    float hh = __ldg(lps_b + t) + __ldg(lpd_b + t);
#pragma unroll 1
    for (int d = 0; d < 64; d++)
        hh += sa[d] * __ldg(lps_w + d * 64 + t) + sb[d] * __ldg(lpd_w + d * 64 + t);
    hh = fmaxf(hh, 0.f);
    float p = hh * __ldg(lpf_w + t);
    p += __shfl_xor_sync(0xffffffffu, p, 16);
    p += __shfl_xor_sync(0xffffffffu, p, 8);
    p += __shfl_xor_sync(0xffffffffu, p, 4);
    p += __shfl_xor_sync(0xffffffffu, p, 2);
    p += __shfl_xor_sync(0xffffffffu, p, 1);
    if ((t & 31) == 0) red[t >> 5] = p;
    __syncthreads();
    if (t == 0) out[b] = red[0] + red[1] + __ldg(lpf_b);
}

// ============================================================================
extern "C" void kernel_launch(void* const* d_in, const int* in_sizes, int n_in,
                              void* d_out, int out_size)
{
    const float* memory      = (const float*)d_in[0];
    const float* pos_memory  = (const float*)d_in[1];
    const float* last_update = (const float*)d_in[2];
    const int*   n_id        = (const int*)  d_in[3];
    const int*   edge_index  = (const int*)  d_in[4];
    const float* edge_t      = (const float*)d_in[5];
    const float* edge_msg    = (const float*)d_in[6];
    const int*   src         = (const int*)  d_in[7];
    const int*   dst         = (const int*)  d_in[8];
    const int*   neg_dst     = (const int*)  d_in[9];
    const float* time_w      = (const float*)d_in[10];
    const float* time_b      = (const float*)d_in[11];
    const float* Wq          = (const float*)d_in[12];
    const float* bq          = (const float*)d_in[13];
    const float* Wk          = (const float*)d_in[14];
    const float* bk          = (const float*)d_in[15];
    const float* Wv          = (const float*)d_in[16];
    const float* bv          = (const float*)d_in[17];
    const float* We          = (const float*)d_in[18];
    const float* be          = (const float*)d_in[19];
    const float* Wskip       = (const float*)d_in[20];
    const float* bskip       = (const float*)d_in[21];
    const float* mlp_w       = (const float*)d_in[22];
    const float* mlp_b       = (const float*)d_in[23];
    const float* lps_w       = (const float*)d_in[24];
    const float* lps_b       = (const float*)d_in[25];
    const float* lpd_w       = (const float*)d_in[26];
    const float* lpd_b       = (const float*)d_in[27];
    const float* lpf_w       = (const float*)d_in[28];
    const float* lpf_b       = (const float*)d_in[29];

    int Nn       = in_sizes[3];   // 65536
    int numNodes = in_sizes[2];   // 100000
    int E        = in_sizes[5];   // 655360
    int Bn       = in_sizes[7];   // 4096
    float* out   = (float*)d_out;

    int initN = Nn * 128;
    k_init<<<(initN + 255) / 256, 256>>>(Nn, numNodes);
    k_scatter<<<(Nn + 255) / 256, 256>>>(n_id, last_update, Nn);

    dim3 gg(4, (unsigned)(Nn >> 7));
    k_node_gemm<<<gg, 128>>>(n_id, memory, pos_memory,
                             Wq, Wk, Wv, Wskip, bq, bk, bv, bskip);

    k_edge<<<(E + 127) / 128, 128>>>(edge_index, edge_t, edge_msg,
                                     We, be, time_w, time_b, E);

    k_node_final<<<(Nn + 63) / 64, 256>>>(mlp_w, mlp_b);

    k_link_pred<<<2 * Bn, 64>>>(src, dst, neg_dst,
                                lps_w, lps_b, lpd_w, lpd_b, lpf_w, lpf_b,
                                out, Bn);
}

// round 12
// speedup vs baseline: 1.4043x; 1.4043x over previous
#include <cuda_runtime.h>
#include <cuda_bf16.h>
#include <math.h>

// Problem-fixed maxima (shapes are fixed by the dataset)
#define NMAX      65536
#define NODESMAX  100000

// ---- scratch (device globals; no dynamic allocation allowed) ----
__device__ float g_qkvs[(size_t)NMAX * 512];   // per node: q[128] | k[128] | v[128] | skip[128]
__device__ float g_agg [(size_t)NMAX * 128];   // unnormalized attention numerator
__device__ float g_den [NMAX * 2];             // per-head softmax denominator
__device__ float g_lu  [NMAX];                 // last_update gathered to local rows
__device__ int   g_assoc[NODESMAX];            // global node id -> local row
__device__ float g_h   [(size_t)NMAX * 64];    // MLP output per node

typedef unsigned long long ull;

// ---- packed f32x2 helpers (sm_103a FFMA2 path) ----
__device__ __forceinline__ ull pack2(float lo, float hi) {
    ull r;
    asm("mov.b64 %0, {%1, %2};" : "=l"(r)
        : "r"(__float_as_uint(lo)), "r"(__float_as_uint(hi)));
    return r;
}
__device__ __forceinline__ void unpack2(ull v, float &lo, float &hi) {
    unsigned int a, b;
    asm("mov.b64 {%0, %1}, %2;" : "=r"(a), "=r"(b) : "l"(v));
    lo = __uint_as_float(a);
    hi = __uint_as_float(b);
}
__device__ __forceinline__ ull fma2(ull a, ull b, ull c) {
    ull d;
    asm("fma.rn.f32x2 %0, %1, %2, %3;" : "=l"(d) : "l"(a), "l"(b), "l"(c));
    return d;
}
__device__ __forceinline__ void red4(float* p, float x, float y, float z, float w) {
    asm volatile("red.global.add.v4.f32 [%0], {%1, %2, %3, %4};"
                 :: "l"(p), "f"(x), "f"(y), "f"(z), "f"(w) : "memory");
}
__device__ __forceinline__ void red1(float* p, float x) {
    asm volatile("red.global.add.f32 [%0], %1;" :: "l"(p), "f"(x) : "memory");
}

// ============================================================================
// K0: zero accumulators, reset assoc
// ============================================================================
__global__ void k_init(int Nn, int numNodes) {
    int i = blockIdx.x * 256 + threadIdx.x;
    int aggN = Nn * 128;
    if (i < aggN)      g_agg[i] = 0.f;
    if (i < Nn * 2)    g_den[i] = 0.f;
    if (i < numNodes)  g_assoc[i] = 0;
}

// ============================================================================
// K1: scatter assoc + gather last_update
// ============================================================================
__global__ void k_scatter(const int* __restrict__ n_id,
                          const float* __restrict__ last_update, int Nn) {
    int i = blockIdx.x * 256 + threadIdx.x;
    if (i < Nn) {
        int g = n_id[i];
        g_assoc[g] = i;
        g_lu[i] = last_update[g];
    }
}

// ============================================================================
// K2: node GEMM.  C[N,512] = z[N,256] @ [Wq|Wk|Wv|Wskip] + bias
//     (R6 body, unchanged: BM=128, BN=128, BK=16, 256 thr, 8x8 micro)
// ============================================================================
__global__ __launch_bounds__(256) void k_node_gemm(
    const int*   __restrict__ n_id,
    const float* __restrict__ memory, const float* __restrict__ pos_memory,
    const float* __restrict__ Wq, const float* __restrict__ Wk,
    const float* __restrict__ Wv, const float* __restrict__ Ws,
    const float* __restrict__ bq, const float* __restrict__ bk,
    const float* __restrict__ bv, const float* __restrict__ bs)
{
    __shared__ __align__(16) float As[16][128];
    __shared__ __align__(16) float Bs[16][128];

    const float* W; const float* bias;
    int bx = blockIdx.x;
    if      (bx == 0) { W = Wq; bias = bq; }
    else if (bx == 1) { W = Wk; bias = bk; }
    else if (bx == 2) { W = Wv; bias = bv; }
    else              { W = Ws; bias = bs; }

    int tid = threadIdx.x;
    int tx = tid & 15;        // col group: cols tx*8 .. tx*8+7
    int ty = tid >> 4;        // row group: rows ty*8 .. ty*8+7
    int row0 = blockIdx.y << 7;

    int lr  = tid >> 2;       // A-load row (0..63), second row lr+64
    int lc4 = (tid & 3) << 2; // A-load col within tile (0,4,8,12)
    int nid0 = n_id[row0 + lr];
    int nid1 = n_id[row0 + lr + 64];

    ull acc[8][4];
#pragma unroll
    for (int i = 0; i < 8; i++)
#pragma unroll
        for (int j = 0; j < 4; j++) acc[i][j] = 0ULL;

    int bk_ = tid >> 5;              // B-load row in tile (0..7), second +8
    int bc  = (tid & 31) << 2;       // B-load col (float4)

    for (int k0 = 0; k0 < 256; k0 += 16) {
        const float* srcm = (k0 < 128) ? memory : pos_memory;
        int kb = k0 & 127;
        float4 a0 = __ldg((const float4*)(srcm + (size_t)nid0 * 128 + kb + lc4));
        float4 a1 = __ldg((const float4*)(srcm + (size_t)nid1 * 128 + kb + lc4));
        float4 b0 = __ldg((const float4*)(W + (size_t)(k0 + bk_) * 128 + bc));
        float4 b1 = __ldg((const float4*)(W + (size_t)(k0 + bk_ + 8) * 128 + bc));
        __syncthreads();
        As[lc4 + 0][lr] = a0.x; As[lc4 + 1][lr] = a0.y;
        As[lc4 + 2][lr] = a0.z; As[lc4 + 3][lr] = a0.w;
        As[lc4 + 0][lr + 64] = a1.x; As[lc4 + 1][lr + 64] = a1.y;
        As[lc4 + 2][lr + 64] = a1.z; As[lc4 + 3][lr + 64] = a1.w;
        *(float4*)&Bs[bk_][bc]     = b0;
        *(float4*)&Bs[bk_ + 8][bc] = b1;
        __syncthreads();
#pragma unroll
        for (int kk = 0; kk < 16; kk++) {
            float a[8];
            *(float4*)&a[0] = *(const float4*)&As[kk][ty * 8];
            *(float4*)&a[4] = *(const float4*)&As[kk][ty * 8 + 4];
            const ull* bp = (const ull*)&Bs[kk][tx * 8];
            ull bv0 = bp[0], bv1 = bp[1], bv2 = bp[2], bv3 = bp[3];
#pragma unroll
            for (int i = 0; i < 8; i++) {
                ull ad = pack2(a[i], a[i]);
                acc[i][0] = fma2(ad, bv0, acc[i][0]);
                acc[i][1] = fma2(ad, bv1, acc[i][1]);
                acc[i][2] = fma2(ad, bv2, acc[i][2]);
                acc[i][3] = fma2(ad, bv3, acc[i][3]);
            }
        }
    }

    float bb[8];
    *(float4*)&bb[0] = __ldg((const float4*)(bias + tx * 8));
    *(float4*)&bb[4] = __ldg((const float4*)(bias + tx * 8 + 4));
#pragma unroll
    for (int i = 0; i < 8; i++) {
        int r = row0 + ty * 8 + i;
        float v[8];
#pragma unroll
        for (int j = 0; j < 4; j++) {
            float lo, hi; unpack2(acc[i][j], lo, hi);
            v[2 * j]     = lo + bb[2 * j];
            v[2 * j + 1] = hi + bb[2 * j + 1];
        }
        float* orow = g_qkvs + (size_t)r * 512 + (bx << 7) + tx * 8;
        *(float4*)&orow[0] = *(float4*)&v[0];
        *(float4*)&orow[4] = *(float4*)&v[4];
    }
}

// ============================================================================
// K3: fused edge kernel (R6 body; epilogue switched to red.global.add.v4.f32).
//   - build edge_attr tile [64 x 16] on the fly (cos time-enc cols 0-63, msg 64-127)
//   - GEMM vs We (staged in smem), e[64][128] stays in registers
//   - epilogue: 16 lanes/edge, score via shfl over 8-lane head groups,
//     ex = exp(score/8); v4 RED accumulation of numerator, scalar RED for den.
// ============================================================================
__global__ __launch_bounds__(256) void k_edge(
    const int*   __restrict__ edge_index, const float* __restrict__ edge_t,
    const float* __restrict__ edge_msg,   const float* __restrict__ We,
    const float* __restrict__ be,         const float* __restrict__ time_w,
    const float* __restrict__ time_b,     int E)
{
    __shared__ int   s_se[64], s_de[64];
    __shared__ float s_rel[64];
    __shared__ float s_tw[64], s_tb[64];
    __shared__ __align__(16) float As[16][64];
    __shared__ __align__(16) float Bs[16][128];

    int tid = threadIdx.x;
    int e0 = blockIdx.x << 6;
    if (tid < 64) {
        int e = e0 + tid;
        int ec = (e < E) ? e : (E - 1);
        int se = edge_index[ec];
        int de = edge_index[E + ec];
        s_se[tid] = se; s_de[tid] = de;
        s_rel[tid] = g_lu[se] - edge_t[ec];
        s_tw[tid] = time_w[tid];
        s_tb[tid] = time_b[tid];
    }
    __syncthreads();

    int tx = tid & 15;   // cols tx*8 .. +7 ; head = tx>>3
    int ty = tid >> 4;   // edges ty*4 .. +3
    int lr = tid >> 2;   // A-load edge row 0..63
    int lc = (tid & 3) << 2;
    int bk_ = tid >> 5;
    int bc  = (tid & 31) << 2;

    ull acc[4][4];
#pragma unroll
    for (int i = 0; i < 4; i++)
#pragma unroll
        for (int j = 0; j < 4; j++) acc[i][j] = 0ULL;

    for (int k0 = 0; k0 < 128; k0 += 16) {
        float av[4];
        if (k0 < 64) {
            float rt = s_rel[lr];
#pragma unroll
            for (int ii = 0; ii < 4; ii++) {
                int c = k0 + lc + ii;
                av[ii] = cosf(rt * s_tw[c] + s_tb[c]);
            }
        } else {
            int er = e0 + lr; if (er >= E) er = E - 1;
            float4 m = __ldg((const float4*)(edge_msg + (size_t)er * 64 + (k0 - 64) + lc));
            av[0] = m.x; av[1] = m.y; av[2] = m.z; av[3] = m.w;
        }
        float4 b0 = __ldg((const float4*)(We + (size_t)(k0 + bk_) * 128 + bc));
        float4 b1 = __ldg((const float4*)(We + (size_t)(k0 + bk_ + 8) * 128 + bc));
        __syncthreads();
        As[lc + 0][lr] = av[0]; As[lc + 1][lr] = av[1];
        As[lc + 2][lr] = av[2]; As[lc + 3][lr] = av[3];
        *(float4*)&Bs[bk_][bc]     = b0;
        *(float4*)&Bs[bk_ + 8][bc] = b1;
        __syncthreads();
#pragma unroll
        for (int kk = 0; kk < 16; kk++) {
            float a[4];
            *(float4*)&a[0] = *(const float4*)&As[kk][ty * 4];
            const ull* bp = (const ull*)&Bs[kk][tx * 8];
            ull bv0 = bp[0], bv1 = bp[1], bv2 = bp[2], bv3 = bp[3];
#pragma unroll
            for (int i = 0; i < 4; i++) {
                ull ad = pack2(a[i], a[i]);
                acc[i][0] = fma2(ad, bv0, acc[i][0]);
                acc[i][1] = fma2(ad, bv1, acc[i][1]);
                acc[i][2] = fma2(ad, bv2, acc[i][2]);
                acc[i][3] = fma2(ad, bv3, acc[i][3]);
            }
        }
    }

    // e = GEMM result + be, kept in registers
    float ev[4][8];
    float beb[8];
    *(float4*)&beb[0] = __ldg((const float4*)(be + tx * 8));
    *(float4*)&beb[4] = __ldg((const float4*)(be + tx * 8 + 4));
#pragma unroll
    for (int i = 0; i < 4; i++)
#pragma unroll
        for (int j = 0; j < 4; j++) {
            float lo, hi; unpack2(acc[i][j], lo, hi);
            ev[i][2 * j]     = lo + beb[2 * j];
            ev[i][2 * j + 1] = hi + beb[2 * j + 1];
        }

    // scores: 16 lanes (same ty) share an edge; lanes tx 0-7 = head0, 8-15 = head1
    float ex[4];
#pragma unroll
    for (int i = 0; i < 4; i++) {
        int el = ty * 4 + i;
        int de = s_de[el], se = s_se[el];
        const float* qp = g_qkvs + (size_t)de * 512 + tx * 8;
        const float* kp = g_qkvs + (size_t)se * 512 + 128 + tx * 8;
        float4 q0 = __ldg((const float4*)qp);
        float4 q1 = __ldg((const float4*)(qp + 4));
        float4 kk0 = __ldg((const float4*)kp);
        float4 kk1 = __ldg((const float4*)(kp + 4));
        float s = q0.x * (kk0.x + ev[i][0]) + q0.y * (kk0.y + ev[i][1])
                + q0.z * (kk0.z + ev[i][2]) + q0.w * (kk0.w + ev[i][3])
                + q1.x * (kk1.x + ev[i][4]) + q1.y * (kk1.y + ev[i][5])
                + q1.z * (kk1.z + ev[i][6]) + q1.w * (kk1.w + ev[i][7]);
        s += __shfl_xor_sync(0xffffffffu, s, 1);
        s += __shfl_xor_sync(0xffffffffu, s, 2);
        s += __shfl_xor_sync(0xffffffffu, s, 4);
        ex[i] = expf(s * 0.125f);   // / sqrt(HD=64)
    }

    // unnormalized accumulation (softmax normalization happens per node later)
#pragma unroll
    for (int i = 0; i < 4; i++) {
        int el = ty * 4 + i;
        if (e0 + el >= E) continue;
        int de = s_de[el], se = s_se[el];
        const float* vp = g_qkvs + (size_t)se * 512 + 256 + tx * 8;
        float4 v0 = __ldg((const float4*)vp);
        float4 v1 = __ldg((const float4*)(vp + 4));
        float* dst = g_agg + (size_t)de * 128 + tx * 8;
        float e_ = ex[i];
        red4(dst + 0, e_ * (v0.x + ev[i][0]), e_ * (v0.y + ev[i][1]),
                      e_ * (v0.z + ev[i][2]), e_ * (v0.w + ev[i][3]));
        red4(dst + 4, e_ * (v1.x + ev[i][4]), e_ * (v1.y + ev[i][5]),
                      e_ * (v1.z + ev[i][6]), e_ * (v1.w + ev[i][7]));
        if      (tx == 0) red1(&g_den[de * 2 + 0], e_);
        else if (tx == 8) red1(&g_den[de * 2 + 1], e_);
    }
}

// ============================================================================
// K4: per-node normalize + skip + MLP -> g_h[N,64].  64 nodes per block,
//     mlp_w staged through smem (weight traffic 2.1GB -> 33MB).
// ============================================================================
__global__ __launch_bounds__(256) void k_node_final(
    const float* __restrict__ mlp_w, const float* __restrict__ mlp_b)
{
    __shared__ float so[64][129];
    __shared__ __align__(16) float sw[16][64];
    int t = threadIdx.x;
    int base = blockIdx.x << 6;

    // stage normalized+skip node features [64 x 128]
#pragma unroll 1
    for (int r = 0; r < 32; r++) {
        int idx = r * 256 + t;
        int nl = idx >> 7, c = idx & 127;
        int node = base + nl;
        float d = g_den[node * 2 + (c >> 6)];
        so[nl][c] = g_agg[(size_t)node * 128 + c] / (d + 1e-16f)
                  + g_qkvs[(size_t)node * 512 + 384 + c];
    }

    int node = t >> 2;           // 0..63
    int col0 = (t & 3) << 4;     // 0,16,32,48
    ull accs[8];
#pragma unroll
    for (int j = 0; j < 8; j++) accs[j] = 0ULL;

#pragma unroll 1
    for (int d0 = 0; d0 < 128; d0 += 16) {
        __syncthreads();
        // load mlp_w chunk [16 x 64]
        {
            int wr = t >> 4, wc = (t & 15) << 2;
            *(float4*)&sw[wr][wc] = __ldg((const float4*)(mlp_w + (size_t)(d0 + wr) * 64 + wc));
        }
        __syncthreads();
#pragma unroll
        for (int d = 0; d < 16; d++) {
            float a0 = so[node][d0 + d];
            ull ad = pack2(a0, a0);
            const ull* wp = (const ull*)&sw[d][col0];
#pragma unroll
            for (int j = 0; j < 8; j++) accs[j] = fma2(ad, wp[j], accs[j]);
        }
    }

    float outv[16];
#pragma unroll
    for (int j = 0; j < 8; j++) {
        float lo, hi; unpack2(accs[j], lo, hi);
        outv[2 * j]     = lo + __ldg(mlp_b + col0 + 2 * j);
        outv[2 * j + 1] = hi + __ldg(mlp_b + col0 + 2 * j + 1);
    }
    float* op = g_h + (size_t)(base + node) * 64 + col0;
#pragma unroll
    for (int j = 0; j < 4; j++)
        *(float4*)&op[4 * j] = *(float4*)&outv[4 * j];
}

// ============================================================================
// K5: link predictor.  blocks [0,B) -> pos (src,dst); [B,2B) -> neg (src,neg_dst)
// ============================================================================
__global__ __launch_bounds__(64) void k_link_pred(
    const int* __restrict__ src, const int* __restrict__ dst,
    const int* __restrict__ neg_dst,
    const float* __restrict__ lps_w, const float* __restrict__ lps_b,
    const float* __restrict__ lpd_w, const float* __restrict__ lpd_b,
    const float* __restrict__ lpf_w, const float* __restrict__ lpf_b,
    float* __restrict__ out, int Bn)
{
    __shared__ float sa[64], sb[64];
    __shared__ float red[2];
    int b = blockIdx.x;
    int t = threadIdx.x;
    int pos = (b < Bn);
    int bb = pos ? b : b - Bn;
    int sn = g_assoc[src[bb]];
    int dn = g_assoc[pos ? dst[bb] : neg_dst[bb]];
    sa[t] = g_h[(size_t)sn * 64 + t];
    sb[t] = g_h[(size_t)dn * 64 + t];
    __syncthreads();
    float hh = __ldg(lps_b + t) + __ldg(lpd_b + t);
#pragma unroll
    for (int d = 0; d < 64; d++)
        hh += sa[d] * __ldg(lps_w + d * 64 + t) + sb[d] * __ldg(lpd_w + d * 64 + t);
    hh = fmaxf(hh, 0.f);
    float p = hh * __ldg(lpf_w + t);
    p += __shfl_xor_sync(0xffffffffu, p, 16);
    p += __shfl_xor_sync(0xffffffffu, p, 8);
    p += __shfl_xor_sync(0xffffffffu, p, 4);
    p += __shfl_xor_sync(0xffffffffu, p, 2);
    p += __shfl_xor_sync(0xffffffffu, p, 1);
    if ((t & 31) == 0) red[t >> 5] = p;
    __syncthreads();
    if (t == 0) out[b] = red[0] + red[1] + __ldg(lpf_b);
}

// ============================================================================
extern "C" void kernel_launch(void* const* d_in, const int* in_sizes, int n_in,
                              void* d_out, int out_size)
{
    const float* memory      = (const float*)d_in[0];
    const float* pos_memory  = (const float*)d_in[1];
    const float* last_update = (const float*)d_in[2];
    const int*   n_id        = (const int*)  d_in[3];
    const int*   edge_index  = (const int*)  d_in[4];
    const float* edge_t      = (const float*)d_in[5];
    const float* edge_msg    = (const float*)d_in[6];
    const int*   src         = (const int*)  d_in[7];
    const int*   dst         = (const int*)  d_in[8];
    const int*   neg_dst     = (const int*)  d_in[9];
    const float* time_w      = (const float*)d_in[10];
    const float* time_b      = (const float*)d_in[11];
    const float* Wq          = (const float*)d_in[12];
    const float* bq          = (const float*)d_in[13];
    const float* Wk          = (const float*)d_in[14];
    const float* bk          = (const float*)d_in[15];
    const float* Wv          = (const float*)d_in[16];
    const float* bv          = (const float*)d_in[17];
    const float* We          = (const float*)d_in[18];
    const float* be          = (const float*)d_in[19];
    const float* Wskip       = (const float*)d_in[20];
    const float* bskip       = (const float*)d_in[21];
    const float* mlp_w       = (const float*)d_in[22];
    const float* mlp_b       = (const float*)d_in[23];
    const float* lps_w       = (const float*)d_in[24];
    const float* lps_b       = (const float*)d_in[25];
    const float* lpd_w       = (const float*)d_in[26];
    const float* lpd_b       = (const float*)d_in[27];
    const float* lpf_w       = (const float*)d_in[28];
    const float* lpf_b       = (const float*)d_in[29];

    int Nn       = in_sizes[3];   // 65536
    int numNodes = in_sizes[2];   // 100000
    int E        = in_sizes[5];   // 655360
    int Bn       = in_sizes[7];   // 4096
    float* out   = (float*)d_out;

    int initN = Nn * 128;
    k_init<<<(initN + 255) / 256, 256>>>(Nn, numNodes);
    k_scatter<<<(Nn + 255) / 256, 256>>>(n_id, last_update, Nn);

    dim3 gg(4, (unsigned)(Nn >> 7));
    k_node_gemm<<<gg, 256>>>(n_id, memory, pos_memory,
                             Wq, Wk, Wv, Wskip, bq, bk, bv, bskip);

    k_edge<<<(E + 63) / 64, 256>>>(edge_index, edge_t, edge_msg,
                                   We, be, time_w, time_b, E);

    k_node_final<<<(Nn + 63) / 64, 256>>>(mlp_w, mlp_b);

    k_link_pred<<<2 * Bn, 64>>>(src, dst, neg_dst,
                                lps_w, lps_b, lpd_w, lpd_b, lpf_w, lpf_b,
                                out, Bn);
}

// round 13
// speedup vs baseline: 1.7437x; 1.2417x over previous
#include <cuda_runtime.h>
#include <cuda_bf16.h>
#include <math.h>

// Problem-fixed maxima (shapes are fixed by the dataset)
#define NMAX      65536
#define NODESMAX  100000

// ---- scratch (device globals; no dynamic allocation allowed) ----
__device__ float g_qkvs[(size_t)NMAX * 512];   // per node: q[128] | k[128] | v[128] | skip[128]
__device__ float g_agg [(size_t)NMAX * 128];   // unnormalized attention numerator
__device__ float g_den [NMAX * 2];             // per-head softmax denominator
__device__ float g_lu  [NMAX];                 // last_update gathered to local rows
__device__ int   g_assoc[NODESMAX];            // global node id -> local row
__device__ float g_h   [(size_t)NMAX * 64];    // MLP output per node

typedef unsigned long long ull;

// ---- packed f32x2 helpers (sm_103a FFMA2 path) ----
__device__ __forceinline__ ull pack2(float lo, float hi) {
    ull r;
    asm("mov.b64 %0, {%1, %2};" : "=l"(r)
        : "r"(__float_as_uint(lo)), "r"(__float_as_uint(hi)));
    return r;
}
__device__ __forceinline__ void unpack2(ull v, float &lo, float &hi) {
    unsigned int a, b;
    asm("mov.b64 {%0, %1}, %2;" : "=r"(a), "=r"(b) : "l"(v));
    lo = __uint_as_float(a);
    hi = __uint_as_float(b);
}
__device__ __forceinline__ ull fma2(ull a, ull b, ull c) {
    ull d;
    asm("fma.rn.f32x2 %0, %1, %2, %3;" : "=l"(d) : "l"(a), "l"(b), "l"(c));
    return d;
}
__device__ __forceinline__ void red4(float* p, float x, float y, float z, float w) {
    asm volatile("red.global.add.v4.f32 [%0], {%1, %2, %3, %4};"
                 :: "l"(p), "f"(x), "f"(y), "f"(z), "f"(w) : "memory");
}
__device__ __forceinline__ void red1(float* p, float x) {
    asm volatile("red.global.add.f32 [%0], %1;" :: "l"(p), "f"(x) : "memory");
}

// ============================================================================
// K0: zero accumulators, reset assoc
// ============================================================================
__global__ void k_init(int Nn, int numNodes) {
    int i = blockIdx.x * 256 + threadIdx.x;
    int aggN = Nn * 128;
    if (i < aggN)      g_agg[i] = 0.f;
    if (i < Nn * 2)    g_den[i] = 0.f;
    if (i < numNodes)  g_assoc[i] = 0;
}

// ============================================================================
// K1: scatter assoc + gather last_update
// ============================================================================
__global__ void k_scatter(const int* __restrict__ n_id,
                          const float* __restrict__ last_update, int Nn) {
    int i = blockIdx.x * 256 + threadIdx.x;
    if (i < Nn) {
        int g = n_id[i];
        g_assoc[g] = i;
        g_lu[i] = last_update[g];
    }
}

// ============================================================================
// K2: node GEMM.  C[N,512] = z[N,256] @ [Wq|Wk|Wv|Wskip] + bias
//     (R6 body, unchanged: BM=128, BN=128, BK=16, 256 thr, 8x8 micro)
// ============================================================================
__global__ __launch_bounds__(256) void k_node_gemm(
    const int*   __restrict__ n_id,
    const float* __restrict__ memory, const float* __restrict__ pos_memory,
    const float* __restrict__ Wq, const float* __restrict__ Wk,
    const float* __restrict__ Wv, const float* __restrict__ Ws,
    const float* __restrict__ bq, const float* __restrict__ bk,
    const float* __restrict__ bv, const float* __restrict__ bs)
{
    __shared__ __align__(16) float As[16][128];
    __shared__ __align__(16) float Bs[16][128];

    const float* W; const float* bias;
    int bx = blockIdx.x;
    if      (bx == 0) { W = Wq; bias = bq; }
    else if (bx == 1) { W = Wk; bias = bk; }
    else if (bx == 2) { W = Wv; bias = bv; }
    else              { W = Ws; bias = bs; }

    int tid = threadIdx.x;
    int tx = tid & 15;        // col group: cols tx*8 .. tx*8+7
    int ty = tid >> 4;        // row group: rows ty*8 .. ty*8+7
    int row0 = blockIdx.y << 7;

    int lr  = tid >> 2;       // A-load row (0..63), second row lr+64
    int lc4 = (tid & 3) << 2; // A-load col within tile (0,4,8,12)
    int nid0 = n_id[row0 + lr];
    int nid1 = n_id[row0 + lr + 64];

    ull acc[8][4];
#pragma unroll
    for (int i = 0; i < 8; i++)
#pragma unroll
        for (int j = 0; j < 4; j++) acc[i][j] = 0ULL;

    int bk_ = tid >> 5;              // B-load row in tile (0..7), second +8
    int bc  = (tid & 31) << 2;       // B-load col (float4)

    for (int k0 = 0; k0 < 256; k0 += 16) {
        const float* srcm = (k0 < 128) ? memory : pos_memory;
        int kb = k0 & 127;
        float4 a0 = __ldg((const float4*)(srcm + (size_t)nid0 * 128 + kb + lc4));
        float4 a1 = __ldg((const float4*)(srcm + (size_t)nid1 * 128 + kb + lc4));
        float4 b0 = __ldg((const float4*)(W + (size_t)(k0 + bk_) * 128 + bc));
        float4 b1 = __ldg((const float4*)(W + (size_t)(k0 + bk_ + 8) * 128 + bc));
        __syncthreads();
        As[lc4 + 0][lr] = a0.x; As[lc4 + 1][lr] = a0.y;
        As[lc4 + 2][lr] = a0.z; As[lc4 + 3][lr] = a0.w;
        As[lc4 + 0][lr + 64] = a1.x; As[lc4 + 1][lr + 64] = a1.y;
        As[lc4 + 2][lr + 64] = a1.z; As[lc4 + 3][lr + 64] = a1.w;
        *(float4*)&Bs[bk_][bc]     = b0;
        *(float4*)&Bs[bk_ + 8][bc] = b1;
        __syncthreads();
#pragma unroll
        for (int kk = 0; kk < 16; kk++) {
            float a[8];
            *(float4*)&a[0] = *(const float4*)&As[kk][ty * 8];
            *(float4*)&a[4] = *(const float4*)&As[kk][ty * 8 + 4];
            const ull* bp = (const ull*)&Bs[kk][tx * 8];
            ull bv0 = bp[0], bv1 = bp[1], bv2 = bp[2], bv3 = bp[3];
#pragma unroll
            for (int i = 0; i < 8; i++) {
                ull ad = pack2(a[i], a[i]);
                acc[i][0] = fma2(ad, bv0, acc[i][0]);
                acc[i][1] = fma2(ad, bv1, acc[i][1]);
                acc[i][2] = fma2(ad, bv2, acc[i][2]);
                acc[i][3] = fma2(ad, bv3, acc[i][3]);
            }
        }
    }

    float bb[8];
    *(float4*)&bb[0] = __ldg((const float4*)(bias + tx * 8));
    *(float4*)&bb[4] = __ldg((const float4*)(bias + tx * 8 + 4));
#pragma unroll
    for (int i = 0; i < 8; i++) {
        int r = row0 + ty * 8 + i;
        float v[8];
#pragma unroll
        for (int j = 0; j < 4; j++) {
            float lo, hi; unpack2(acc[i][j], lo, hi);
            v[2 * j]     = lo + bb[2 * j];
            v[2 * j + 1] = hi + bb[2 * j + 1];
        }
        float* orow = g_qkvs + (size_t)r * 512 + (bx << 7) + tx * 8;
        *(float4*)&orow[0] = *(float4*)&v[0];
        *(float4*)&orow[4] = *(float4*)&v[4];
    }
}

// ============================================================================
// K3: fused edge kernel.  BM=128 edges/block, 256 threads, 8edge x 8col micro
//     (double arithmetic intensity per LDS byte vs R12's 4x8).
//   - build edge_attr tile [128 x 16] on the fly (cos time-enc cols 0-63, msg)
//   - GEMM vs We (staged in smem), e stays in registers (unpacked per-edge)
//   - epilogue (identical structure to R12): 16 lanes/edge, shfl over 8-lane
//     head groups, exp(score/8), v4 RED numerator + scalar RED denominator.
// ============================================================================
__global__ __launch_bounds__(256, 2) void k_edge(
    const int*   __restrict__ edge_index, const float* __restrict__ edge_t,
    const float* __restrict__ edge_msg,   const float* __restrict__ We,
    const float* __restrict__ be,         const float* __restrict__ time_w,
    const float* __restrict__ time_b,     int E)
{
    __shared__ int   s_se[128], s_de[128];
    __shared__ float s_rel[128];
    __shared__ float s_tw[64], s_tb[64];
    __shared__ __align__(16) float As[16][128];
    __shared__ __align__(16) float Bs[16][128];

    int tid = threadIdx.x;
    int e0 = blockIdx.x << 7;
    if (tid < 128) {
        int e = e0 + tid;
        int ec = (e < E) ? e : (E - 1);
        int se = edge_index[ec];
        int de = edge_index[E + ec];
        s_se[tid] = se; s_de[tid] = de;
        s_rel[tid] = g_lu[se] - edge_t[ec];
    } else if (tid < 192) {
        s_tw[tid - 128] = time_w[tid - 128];
        s_tb[tid - 128] = time_b[tid - 128];
    }
    __syncthreads();

    int tx = tid & 15;   // cols tx*8 .. +7 ; head = tx>>3
    int ty = tid >> 4;   // edges ty*8 .. +7
    int lr = tid >> 1;   // A-load edge row 0..127
    int lc = (tid & 1) << 3;   // A-load col 0 or 8
    int bk_ = tid >> 5;
    int bc  = (tid & 31) << 2;

    ull acc[8][4];
#pragma unroll
    for (int i = 0; i < 8; i++)
#pragma unroll
        for (int j = 0; j < 4; j++) acc[i][j] = 0ULL;

    for (int k0 = 0; k0 < 128; k0 += 16) {
        float av[8];
        if (k0 < 64) {
            float rt = s_rel[lr];
#pragma unroll
            for (int ii = 0; ii < 8; ii++) {
                int c = k0 + lc + ii;
                av[ii] = cosf(rt * s_tw[c] + s_tb[c]);
            }
        } else {
            int er = e0 + lr; if (er >= E) er = E - 1;
            float4 m0 = __ldg((const float4*)(edge_msg + (size_t)er * 64 + (k0 - 64) + lc));
            float4 m1 = __ldg((const float4*)(edge_msg + (size_t)er * 64 + (k0 - 64) + lc + 4));
            av[0] = m0.x; av[1] = m0.y; av[2] = m0.z; av[3] = m0.w;
            av[4] = m1.x; av[5] = m1.y; av[6] = m1.z; av[7] = m1.w;
        }
        float4 b0 = __ldg((const float4*)(We + (size_t)(k0 + bk_) * 128 + bc));
        float4 b1 = __ldg((const float4*)(We + (size_t)(k0 + bk_ + 8) * 128 + bc));
        __syncthreads();
#pragma unroll
        for (int ii = 0; ii < 8; ii++) As[lc + ii][lr] = av[ii];
        *(float4*)&Bs[bk_][bc]     = b0;
        *(float4*)&Bs[bk_ + 8][bc] = b1;
        __syncthreads();
#pragma unroll
        for (int kk = 0; kk < 16; kk++) {
            float a8[8];
            *(float4*)&a8[0] = *(const float4*)&As[kk][ty * 8];
            *(float4*)&a8[4] = *(const float4*)&As[kk][ty * 8 + 4];
            const ull* bp = (const ull*)&Bs[kk][tx * 8];
            ull bv0 = bp[0], bv1 = bp[1], bv2 = bp[2], bv3 = bp[3];
#pragma unroll
            for (int i = 0; i < 8; i++) {
                ull ad = pack2(a8[i], a8[i]);
                acc[i][0] = fma2(ad, bv0, acc[i][0]);
                acc[i][1] = fma2(ad, bv1, acc[i][1]);
                acc[i][2] = fma2(ad, bv2, acc[i][2]);
                acc[i][3] = fma2(ad, bv3, acc[i][3]);
            }
        }
    }

    float beb[8];
    *(float4*)&beb[0] = __ldg((const float4*)(be + tx * 8));
    *(float4*)&beb[4] = __ldg((const float4*)(be + tx * 8 + 4));

    // epilogue: 16 lanes (same ty) share an edge; lanes tx 0-7 = head0, 8-15 = head1
#pragma unroll
    for (int i = 0; i < 8; i++) {
        int el = ty * 8 + i;
        int de = s_de[el], se = s_se[el];
        float evv[8];
#pragma unroll
        for (int j = 0; j < 4; j++) {
            float lo, hi; unpack2(acc[i][j], lo, hi);
            evv[2 * j]     = lo + beb[2 * j];
            evv[2 * j + 1] = hi + beb[2 * j + 1];
        }
        const float* qp = g_qkvs + (size_t)de * 512 + tx * 8;
        const float* kp = g_qkvs + (size_t)se * 512 + 128 + tx * 8;
        float4 q0 = __ldg((const float4*)qp);
        float4 q1 = __ldg((const float4*)(qp + 4));
        float4 kk0 = __ldg((const float4*)kp);
        float4 kk1 = __ldg((const float4*)(kp + 4));
        float s = q0.x * (kk0.x + evv[0]) + q0.y * (kk0.y + evv[1])
                + q0.z * (kk0.z + evv[2]) + q0.w * (kk0.w + evv[3])
                + q1.x * (kk1.x + evv[4]) + q1.y * (kk1.y + evv[5])
                + q1.z * (kk1.z + evv[6]) + q1.w * (kk1.w + evv[7]);
        s += __shfl_xor_sync(0xffffffffu, s, 1);
        s += __shfl_xor_sync(0xffffffffu, s, 2);
        s += __shfl_xor_sync(0xffffffffu, s, 4);
        float ex = expf(s * 0.125f);   // / sqrt(HD=64)

        if (e0 + el < E) {
            const float* vp = g_qkvs + (size_t)se * 512 + 256 + tx * 8;
            float4 v0 = __ldg((const float4*)vp);
            float4 v1 = __ldg((const float4*)(vp + 4));
            float* dst = g_agg + (size_t)de * 128 + tx * 8;
            red4(dst + 0, ex * (v0.x + evv[0]), ex * (v0.y + evv[1]),
                          ex * (v0.z + evv[2]), ex * (v0.w + evv[3]));
            red4(dst + 4, ex * (v1.x + evv[4]), ex * (v1.y + evv[5]),
                          ex * (v1.z + evv[6]), ex * (v1.w + evv[7]));
            if      (tx == 0) red1(&g_den[de * 2 + 0], ex);
            else if (tx == 8) red1(&g_den[de * 2 + 1], ex);
        }
    }
}

// ============================================================================
// K4: per-node normalize + skip + MLP -> g_h[N,64].  64 nodes per block,
//     mlp_w staged through smem (weight traffic 2.1GB -> 33MB).
// ============================================================================
__global__ __launch_bounds__(256) void k_node_final(
    const float* __restrict__ mlp_w, const float* __restrict__ mlp_b)
{
    __shared__ float so[64][129];
    __shared__ __align__(16) float sw[16][64];
    int t = threadIdx.x;
    int base = blockIdx.x << 6;

    // stage normalized+skip node features [64 x 128]
#pragma unroll 1
    for (int r = 0; r < 32; r++) {
        int idx = r * 256 + t;
        int nl = idx >> 7, c = idx & 127;
        int node = base + nl;
        float d = g_den[node * 2 + (c >> 6)];
        so[nl][c] = g_agg[(size_t)node * 128 + c] / (d + 1e-16f)
                  + g_qkvs[(size_t)node * 512 + 384 + c];
    }

    int node = t >> 2;           // 0..63
    int col0 = (t & 3) << 4;     // 0,16,32,48
    ull accs[8];
#pragma unroll
    for (int j = 0; j < 8; j++) accs[j] = 0ULL;

#pragma unroll 1
    for (int d0 = 0; d0 < 128; d0 += 16) {
        __syncthreads();
        // load mlp_w chunk [16 x 64]
        {
            int wr = t >> 4, wc = (t & 15) << 2;
            *(float4*)&sw[wr][wc] = __ldg((const float4*)(mlp_w + (size_t)(d0 + wr) * 64 + wc));
        }
        __syncthreads();
#pragma unroll
        for (int d = 0; d < 16; d++) {
            float a0 = so[node][d0 + d];
            ull ad = pack2(a0, a0);
            const ull* wp = (const ull*)&sw[d][col0];
#pragma unroll
            for (int j = 0; j < 8; j++) accs[j] = fma2(ad, wp[j], accs[j]);
        }
    }

    float outv[16];
#pragma unroll
    for (int j = 0; j < 8; j++) {
        float lo, hi; unpack2(accs[j], lo, hi);
        outv[2 * j]     = lo + __ldg(mlp_b + col0 + 2 * j);
        outv[2 * j + 1] = hi + __ldg(mlp_b + col0 + 2 * j + 1);
    }
    float* op = g_h + (size_t)(base + node) * 64 + col0;
#pragma unroll
    for (int j = 0; j < 4; j++)
        *(float4*)&op[4 * j] = *(float4*)&outv[4 * j];
}

// ============================================================================
// K5: link predictor.  blocks [0,B) -> pos (src,dst); [B,2B) -> neg (src,neg_dst)
// ============================================================================
__global__ __launch_bounds__(64) void k_link_pred(
    const int* __restrict__ src, const int* __restrict__ dst,
    const int* __restrict__ neg_dst,
    const float* __restrict__ lps_w, const float* __restrict__ lps_b,
    const float* __restrict__ lpd_w, const float* __restrict__ lpd_b,
    const float* __restrict__ lpf_w, const float* __restrict__ lpf_b,
    float* __restrict__ out, int Bn)
{
    __shared__ float sa[64], sb[64];
    __shared__ float red[2];
    int b = blockIdx.x;
    int t = threadIdx.x;
    int pos = (b < Bn);
    int bb = pos ? b : b - Bn;
    int sn = g_assoc[src[bb]];
    int dn = g_assoc[pos ? dst[bb] : neg_dst[bb]];
    sa[t] = g_h[(size_t)sn * 64 + t];
    sb[t] = g_h[(size_t)dn * 64 + t];
    __syncthreads();
    float hh = __ldg(lps_b + t) + __ldg(lpd_b + t);
#pragma unroll
    for (int d = 0; d < 64; d++)
        hh += sa[d] * __ldg(lps_w + d * 64 + t) + sb[d] * __ldg(lpd_w + d * 64 + t);
    hh = fmaxf(hh, 0.f);
    float p = hh * __ldg(lpf_w + t);
    p += __shfl_xor_sync(0xffffffffu, p, 16);
    p += __shfl_xor_sync(0xffffffffu, p, 8);
    p += __shfl_xor_sync(0xffffffffu, p, 4);
    p += __shfl_xor_sync(0xffffffffu, p, 2);
    p += __shfl_xor_sync(0xffffffffu, p, 1);
    if ((t & 31) == 0) red[t >> 5] = p;
    __syncthreads();
    if (t == 0) out[b] = red[0] + red[1] + __ldg(lpf_b);
}

// ============================================================================
extern "C" void kernel_launch(void* const* d_in, const int* in_sizes, int n_in,
                              void* d_out, int out_size)
{
    const float* memory      = (const float*)d_in[0];
    const float* pos_memory  = (const float*)d_in[1];
    const float* last_update = (const float*)d_in[2];
    const int*   n_id        = (const int*)  d_in[3];
    const int*   edge_index  = (const int*)  d_in[4];
    const float* edge_t      = (const float*)d_in[5];
    const float* edge_msg    = (const float*)d_in[6];
    const int*   src         = (const int*)  d_in[7];
    const int*   dst         = (const int*)  d_in[8];
    const int*   neg_dst     = (const int*)  d_in[9];
    const float* time_w      = (const float*)d_in[10];
    const float* time_b      = (const float*)d_in[11];
    const float* Wq          = (const float*)d_in[12];
    const float* bq          = (const float*)d_in[13];
    const float* Wk          = (const float*)d_in[14];
    const float* bk          = (const float*)d_in[15];
    const float* Wv          = (const float*)d_in[16];
    const float* bv          = (const float*)d_in[17];
    const float* We          = (const float*)d_in[18];
    const float* be          = (const float*)d_in[19];
    const float* Wskip       = (const float*)d_in[20];
    const float* bskip       = (const float*)d_in[21];
    const float* mlp_w       = (const float*)d_in[22];
    const float* mlp_b       = (const float*)d_in[23];
    const float* lps_w       = (const float*)d_in[24];
    const float* lps_b       = (const float*)d_in[25];
    const float* lpd_w       = (const float*)d_in[26];
    const float* lpd_b       = (const float*)d_in[27];
    const float* lpf_w       = (const float*)d_in[28];
    const float* lpf_b       = (const float*)d_in[29];

    int Nn       = in_sizes[3];   // 65536
    int numNodes = in_sizes[2];   // 100000
    int E        = in_sizes[5];   // 655360
    int Bn       = in_sizes[7];   // 4096
    float* out   = (float*)d_out;

    int initN = Nn * 128;
    k_init<<<(initN + 255) / 256, 256>>>(Nn, numNodes);
    k_scatter<<<(Nn + 255) / 256, 256>>>(n_id, last_update, Nn);

    dim3 gg(4, (unsigned)(Nn >> 7));
    k_node_gemm<<<gg, 256>>>(n_id, memory, pos_memory,
                             Wq, Wk, Wv, Wskip, bq, bk, bv, bskip);

    k_edge<<<(E + 127) / 128, 256>>>(edge_index, edge_t, edge_msg,
                                     We, be, time_w, time_b, E);

    k_node_final<<<(Nn + 63) / 64, 256>>>(mlp_w, mlp_b);

    k_link_pred<<<2 * Bn, 64>>>(src, dst, neg_dst,
                                lps_w, lps_b, lpd_w, lpd_b, lpf_w, lpf_b,
                                out, Bn);
}

// round 15
// speedup vs baseline: 4.4364x; 2.5442x over previous
#include <cuda_runtime.h>
#include <cuda_bf16.h>
#include <math.h>

// Problem-fixed maxima (shapes are fixed by the dataset)
#define NMAX      65536
#define NODESMAX  100000
#define EMAX      655360

// ---- scratch (device globals; no dynamic allocation allowed) ----
__device__ float g_qkvs[(size_t)NMAX * 512];   // per node: q[128] | k[128] | v[128] | skip[128]
__device__ float g_agg [(size_t)NMAX * 128];   // unnormalized attention numerator
__device__ float g_den [NMAX * 2];             // per-head softmax denominator
__device__ float g_lu  [NMAX];                 // last_update gathered to local rows
__device__ int   g_assoc[NODESMAX];            // global node id -> local row
__device__ float g_h   [(size_t)NMAX * 64];    // MLP output per node
__device__ int   g_mark[NMAX];                 // 1 if node row feeds the output
__device__ int   g_node_list[NMAX];            // compacted marked node rows
__device__ int   g_edge_list[EMAX];            // compacted edges with marked de
__device__ int   g_ncnt;                       // marked node count
__device__ int   g_ecnt;                       // kept edge count

typedef unsigned long long ull;

// ---- packed f32x2 helpers (sm_103a FFMA2 path) ----
__device__ __forceinline__ ull pack2(float lo, float hi) {
    ull r;
    asm("mov.b64 %0, {%1, %2};" : "=l"(r)
        : "r"(__float_as_uint(lo)), "r"(__float_as_uint(hi)));
    return r;
}
__device__ __forceinline__ void unpack2(ull v, float &lo, float &hi) {
    unsigned int a, b;
    asm("mov.b64 {%0, %1}, %2;" : "=r"(a), "=r"(b) : "l"(v));
    lo = __uint_as_float(a);
    hi = __uint_as_float(b);
}
__device__ __forceinline__ ull fma2(ull a, ull b, ull c) {
    ull d;
    asm("fma.rn.f32x2 %0, %1, %2, %3;" : "=l"(d) : "l"(a), "l"(b), "l"(c));
    return d;
}
__device__ __forceinline__ void red4(float* p, float x, float y, float z, float w) {
    asm volatile("red.global.add.v4.f32 [%0], {%1, %2, %3, %4};"
                 :: "l"(p), "f"(x), "f"(y), "f"(z), "f"(w) : "memory");
}
__device__ __forceinline__ void red1(float* p, float x) {
    asm volatile("red.global.add.f32 [%0], %1;" :: "l"(p), "f"(x) : "memory");
}

// ============================================================================
// K0: zero accumulators, marks, lists, counts
// ============================================================================
__global__ void k_init(int Nn, int numNodes) {
    int i = blockIdx.x * 256 + threadIdx.x;
    int aggN = Nn * 128;
    if (i < aggN)      g_agg[i] = 0.f;
    if (i < Nn * 2)    g_den[i] = 0.f;
    if (i < numNodes)  g_assoc[i] = 0;
    if (i < Nn)      { g_mark[i] = 0; g_node_list[i] = 0; }
    if (i == 0)      { g_ncnt = 0; g_ecnt = 0; }
}

// ============================================================================
// K1: scatter assoc + gather last_update
// ============================================================================
__global__ void k_scatter(const int* __restrict__ n_id,
                          const float* __restrict__ last_update, int Nn) {
    int i = blockIdx.x * 256 + threadIdx.x;
    if (i < Nn) {
        int g = n_id[i];
        g_assoc[g] = i;
        g_lu[i] = last_update[g];
    }
}

// ============================================================================
// K1b: mark local rows referenced by the link-pred batch
// ============================================================================
__global__ void k_mark(const int* __restrict__ src, const int* __restrict__ dst,
                       const int* __restrict__ neg, int Bn) {
    int i = blockIdx.x * 256 + threadIdx.x;
    if      (i < Bn)     g_mark[g_assoc[src[i]]] = 1;
    else if (i < 2 * Bn) g_mark[g_assoc[dst[i - Bn]]] = 1;
    else if (i < 3 * Bn) g_mark[g_assoc[neg[i - 2 * Bn]]] = 1;
}

// ============================================================================
// K1c/K1d: compact marked nodes / edges whose destination is marked
// ============================================================================
__global__ void k_compact_nodes(int Nn) {
    int i = blockIdx.x * 256 + threadIdx.x;
    if (i < Nn && g_mark[i]) {
        int p = atomicAdd(&g_ncnt, 1);
        g_node_list[p] = i;
    }
}
__global__ void k_compact_edges(const int* __restrict__ edge_index, int E) {
    int e = blockIdx.x * 256 + threadIdx.x;
    if (e < E && g_mark[edge_index[E + e]]) {
        int p = atomicAdd(&g_ecnt, 1);
        g_edge_list[p] = e;
    }
}

// ============================================================================
// K2: node GEMM.  C = z @ [Wq|Wk|Wv|Wskip] + bias
//     bx 1 (k) / 2 (v): all rows.  bx 0 (q) / 3 (skip): marked rows only,
//     via g_node_list (blocks past g_ncnt exit; tail entries clamp to row 0,
//     producing duplicate identical-value writes — benign).
//     (R6 body: BM=128, BN=128, BK=16, 256 thr, 8x8 micro)
// ============================================================================
__global__ __launch_bounds__(256) void k_node_gemm(
    const int*   __restrict__ n_id,
    const float* __restrict__ memory, const float* __restrict__ pos_memory,
    const float* __restrict__ Wq, const float* __restrict__ Wk,
    const float* __restrict__ Wv, const float* __restrict__ Ws,
    const float* __restrict__ bq, const float* __restrict__ bk,
    const float* __restrict__ bv, const float* __restrict__ bs)
{
    __shared__ __align__(16) float As[16][128];
    __shared__ __align__(16) float Bs[16][128];
    __shared__ int s_rows[128];

    const float* W; const float* bias;
    int bx = blockIdx.x;
    if      (bx == 0) { W = Wq; bias = bq; }
    else if (bx == 1) { W = Wk; bias = bk; }
    else if (bx == 2) { W = Wv; bias = bv; }
    else              { W = Ws; bias = bs; }

    int row0 = blockIdx.y << 7;
    bool sel = (bx == 0) || (bx == 3);
    if (sel && row0 >= g_ncnt) return;

    int tid = threadIdx.x;
    if (tid < 128)
        s_rows[tid] = sel ? g_node_list[row0 + tid] : (row0 + tid);
    __syncthreads();

    int tx = tid & 15;        // col group: cols tx*8 .. tx*8+7
    int ty = tid >> 4;        // row group: rows ty*8 .. ty*8+7

    int lr  = tid >> 2;       // A-load row (0..63), second row lr+64
    int lc4 = (tid & 3) << 2; // A-load col within tile (0,4,8,12)
    int nid0 = n_id[s_rows[lr]];
    int nid1 = n_id[s_rows[lr + 64]];

    ull acc[8][4];
#pragma unroll
    for (int i = 0; i < 8; i++)
#pragma unroll
        for (int j = 0; j < 4; j++) acc[i][j] = 0ULL;

    int bk_ = tid >> 5;              // B-load row in tile (0..7), second +8
    int bc  = (tid & 31) << 2;       // B-load col (float4)

    for (int k0 = 0; k0 < 256; k0 += 16) {
        const float* srcm = (k0 < 128) ? memory : pos_memory;
        int kb = k0 & 127;
        float4 a0 = __ldg((const float4*)(srcm + (size_t)nid0 * 128 + kb + lc4));
        float4 a1 = __ldg((const float4*)(srcm + (size_t)nid1 * 128 + kb + lc4));
        float4 b0 = __ldg((const float4*)(W + (size_t)(k0 + bk_) * 128 + bc));
        float4 b1 = __ldg((const float4*)(W + (size_t)(k0 + bk_ + 8) * 128 + bc));
        __syncthreads();
        As[lc4 + 0][lr] = a0.x; As[lc4 + 1][lr] = a0.y;
        As[lc4 + 2][lr] = a0.z; As[lc4 + 3][lr] = a0.w;
        As[lc4 + 0][lr + 64] = a1.x; As[lc4 + 1][lr + 64] = a1.y;
        As[lc4 + 2][lr + 64] = a1.z; As[lc4 + 3][lr + 64] = a1.w;
        *(float4*)&Bs[bk_][bc]     = b0;
        *(float4*)&Bs[bk_ + 8][bc] = b1;
        __syncthreads();
#pragma unroll
        for (int kk = 0; kk < 16; kk++) {
            float a[8];
            *(float4*)&a[0] = *(const float4*)&As[kk][ty * 8];
            *(float4*)&a[4] = *(const float4*)&As[kk][ty * 8 + 4];
            const ull* bp = (const ull*)&Bs[kk][tx * 8];
            ull bv0 = bp[0], bv1 = bp[1], bv2 = bp[2], bv3 = bp[3];
#pragma unroll
            for (int i = 0; i < 8; i++) {
                ull ad = pack2(a[i], a[i]);
                acc[i][0] = fma2(ad, bv0, acc[i][0]);
                acc[i][1] = fma2(ad, bv1, acc[i][1]);
                acc[i][2] = fma2(ad, bv2, acc[i][2]);
                acc[i][3] = fma2(ad, bv3, acc[i][3]);
            }
        }
    }

    float bb[8];
    *(float4*)&bb[0] = __ldg((const float4*)(bias + tx * 8));
    *(float4*)&bb[4] = __ldg((const float4*)(bias + tx * 8 + 4));
#pragma unroll
    for (int i = 0; i < 8; i++) {
        int r = s_rows[ty * 8 + i];
        float v[8];
#pragma unroll
        for (int j = 0; j < 4; j++) {
            float lo, hi; unpack2(acc[i][j], lo, hi);
            v[2 * j]     = lo + bb[2 * j];
            v[2 * j + 1] = hi + bb[2 * j + 1];
        }
        float* orow = g_qkvs + (size_t)r * 512 + (bx << 7) + tx * 8;
        *(float4*)&orow[0] = *(float4*)&v[0];
        *(float4*)&orow[4] = *(float4*)&v[4];
    }
}

// ============================================================================
// K3: fused edge kernel over COMPACTED edges (marked destinations only).
//     BM=128 list entries/block, 256 threads, 8edge x 8col micro (R13 shape).
// ============================================================================
__global__ __launch_bounds__(256, 2) void k_edge(
    const int*   __restrict__ edge_index, const float* __restrict__ edge_t,
    const float* __restrict__ edge_msg,   const float* __restrict__ We,
    const float* __restrict__ be,         const float* __restrict__ time_w,
    const float* __restrict__ time_b,     int E)
{
    __shared__ int   s_se[128], s_de[128], s_eid[128];
    __shared__ float s_rel[128];
    __shared__ float s_tw[64], s_tb[64];
    __shared__ __align__(16) float As[16][128];
    __shared__ __align__(16) float Bs[16][128];

    int ecnt = g_ecnt;
    int e0 = blockIdx.x << 7;
    if (e0 >= ecnt) return;

    int tid = threadIdx.x;
    if (tid < 128) {
        int idx = e0 + tid;
        int eid = g_edge_list[idx < ecnt ? idx : ecnt - 1];
        s_eid[tid] = eid;
        int se = edge_index[eid];
        int de = edge_index[E + eid];
        s_se[tid] = se; s_de[tid] = de;
        s_rel[tid] = g_lu[se] - edge_t[eid];
    } else if (tid < 192) {
        s_tw[tid - 128] = time_w[tid - 128];
        s_tb[tid - 128] = time_b[tid - 128];
    }
    __syncthreads();

    int tx = tid & 15;   // cols tx*8 .. +7 ; head = tx>>3
    int ty = tid >> 4;   // edges ty*8 .. +7
    int lr = tid >> 1;   // A-load edge row 0..127
    int lc = (tid & 1) << 3;   // A-load col 0 or 8
    int bk_ = tid >> 5;
    int bc  = (tid & 31) << 2;

    ull acc[8][4];
#pragma unroll
    for (int i = 0; i < 8; i++)
#pragma unroll
        for (int j = 0; j < 4; j++) acc[i][j] = 0ULL;

    for (int k0 = 0; k0 < 128; k0 += 16) {
        float av[8];
        if (k0 < 64) {
            float rt = s_rel[lr];
#pragma unroll
            for (int ii = 0; ii < 8; ii++) {
                int c = k0 + lc + ii;
                av[ii] = cosf(rt * s_tw[c] + s_tb[c]);
            }
        } else {
            int er = s_eid[lr];
            float4 m0 = __ldg((const float4*)(edge_msg + (size_t)er * 64 + (k0 - 64) + lc));
            float4 m1 = __ldg((const float4*)(edge_msg + (size_t)er * 64 + (k0 - 64) + lc + 4));
            av[0] = m0.x; av[1] = m0.y; av[2] = m0.z; av[3] = m0.w;
            av[4] = m1.x; av[5] = m1.y; av[6] = m1.z; av[7] = m1.w;
        }
        float4 b0 = __ldg((const float4*)(We + (size_t)(k0 + bk_) * 128 + bc));
        float4 b1 = __ldg((const float4*)(We + (size_t)(k0 + bk_ + 8) * 128 + bc));
        __syncthreads();
#pragma unroll
        for (int ii = 0; ii < 8; ii++) As[lc + ii][lr] = av[ii];
        *(float4*)&Bs[bk_][bc]     = b0;
        *(float4*)&Bs[bk_ + 8][bc] = b1;
        __syncthreads();
#pragma unroll
        for (int kk = 0; kk < 16; kk++) {
            float a8[8];
            *(float4*)&a8[0] = *(const float4*)&As[kk][ty * 8];
            *(float4*)&a8[4] = *(const float4*)&As[kk][ty * 8 + 4];
            const ull* bp = (const ull*)&Bs[kk][tx * 8];
            ull bv0 = bp[0], bv1 = bp[1], bv2 = bp[2], bv3 = bp[3];
#pragma unroll
            for (int i = 0; i < 8; i++) {
                ull ad = pack2(a8[i], a8[i]);
                acc[i][0] = fma2(ad, bv0, acc[i][0]);
                acc[i][1] = fma2(ad, bv1, acc[i][1]);
                acc[i][2] = fma2(ad, bv2, acc[i][2]);
                acc[i][3] = fma2(ad, bv3, acc[i][3]);
            }
        }
    }

    float beb[8];
    *(float4*)&beb[0] = __ldg((const float4*)(be + tx * 8));
    *(float4*)&beb[4] = __ldg((const float4*)(be + tx * 8 + 4));

    // epilogue: 16 lanes (same ty) share an edge; lanes tx 0-7 = head0, 8-15 = head1
#pragma unroll
    for (int i = 0; i < 8; i++) {
        int el = ty * 8 + i;
        int de = s_de[el], se = s_se[el];
        float evv[8];
#pragma unroll
        for (int j = 0; j < 4; j++) {
            float lo, hi; unpack2(acc[i][j], lo, hi);
            evv[2 * j]     = lo + beb[2 * j];
            evv[2 * j + 1] = hi + beb[2 * j + 1];
        }
        const float* qp = g_qkvs + (size_t)de * 512 + tx * 8;
        const float* kp = g_qkvs + (size_t)se * 512 + 128 + tx * 8;
        float4 q0 = __ldg((const float4*)qp);
        float4 q1 = __ldg((const float4*)(qp + 4));
        float4 kk0 = __ldg((const float4*)kp);
        float4 kk1 = __ldg((const float4*)(kp + 4));
        float s = q0.x * (kk0.x + evv[0]) + q0.y * (kk0.y + evv[1])
                + q0.z * (kk0.z + evv[2]) + q0.w * (kk0.w + evv[3])
                + q1.x * (kk1.x + evv[4]) + q1.y * (kk1.y + evv[5])
                + q1.z * (kk1.z + evv[6]) + q1.w * (kk1.w + evv[7]);
        s += __shfl_xor_sync(0xffffffffu, s, 1);
        s += __shfl_xor_sync(0xffffffffu, s, 2);
        s += __shfl_xor_sync(0xffffffffu, s, 4);
        float ex = expf(s * 0.125f);   // / sqrt(HD=64)

        if (e0 + el < ecnt) {
            const float* vp = g_qkvs + (size_t)se * 512 + 256 + tx * 8;
            float4 v0 = __ldg((const float4*)vp);
            float4 v1 = __ldg((const float4*)(vp + 4));
            float* dst = g_agg + (size_t)de * 128 + tx * 8;
            red4(dst + 0, ex * (v0.x + evv[0]), ex * (v0.y + evv[1]),
                          ex * (v0.z + evv[2]), ex * (v0.w + evv[3]));
            red4(dst + 4, ex * (v1.x + evv[4]), ex * (v1.y + evv[5]),
                          ex * (v1.z + evv[6]), ex * (v1.w + evv[7]));
            if      (tx == 0) red1(&g_den[de * 2 + 0], ex);
            else if (tx == 8) red1(&g_den[de * 2 + 1], ex);
        }
    }
}

// ============================================================================
// K4: normalize + skip + MLP -> g_h, MARKED nodes only (64 list entries/block)
// ============================================================================
__global__ __launch_bounds__(256) void k_node_final(
    const float* __restrict__ mlp_w, const float* __restrict__ mlp_b)
{
    __shared__ float so[64][129];
    __shared__ __align__(16) float sw[16][64];
    __shared__ int s_nodes[64];
    int ncnt = g_ncnt;
    int base = blockIdx.x << 6;
    if (base >= ncnt) return;

    int t = threadIdx.x;
    if (t < 64) s_nodes[t] = g_node_list[base + t];
    __syncthreads();

    // stage normalized+skip node features [64 x 128]
#pragma unroll 1
    for (int r = 0; r < 32; r++) {
        int idx = r * 256 + t;
        int nl = idx >> 7, c = idx & 127;
        int node = s_nodes[nl];
        float d = g_den[node * 2 + (c >> 6)];
        so[nl][c] = g_agg[(size_t)node * 128 + c] / (d + 1e-16f)
                  + g_qkvs[(size_t)node * 512 + 384 + c];
    }

    int nl  = t >> 2;            // 0..63
    int col0 = (t & 3) << 4;     // 0,16,32,48
    ull accs[8];
#pragma unroll
    for (int j = 0; j < 8; j++) accs[j] = 0ULL;

#pragma unroll 1
    for (int d0 = 0; d0 < 128; d0 += 16) {
        __syncthreads();
        // load mlp_w chunk [16 x 64]
        {
            int wr = t >> 4, wc = (t & 15) << 2;
            *(float4*)&sw[wr][wc] = __ldg((const float4*)(mlp_w + (size_t)(d0 + wr) * 64 + wc));
        }
        __syncthreads();
#pragma unroll
        for (int d = 0; d < 16; d++) {
            float a0 = so[nl][d0 + d];
            ull ad = pack2(a0, a0);
            const ull* wp = (const ull*)&sw[d][col0];
#pragma unroll
            for (int j = 0; j < 8; j++) accs[j] = fma2(ad, wp[j], accs[j]);
        }
    }

    float outv[16];
#pragma unroll
    for (int j = 0; j < 8; j++) {
        float lo, hi; unpack2(accs[j], lo, hi);
        outv[2 * j]     = lo + __ldg(mlp_b + col0 + 2 * j);
        outv[2 * j + 1] = hi + __ldg(mlp_b + col0 + 2 * j + 1);
    }
    float* op = g_h + (size_t)s_nodes[nl] * 64 + col0;
#pragma unroll
    for (int j = 0; j < 4; j++)
        *(float4*)&op[4 * j] = *(float4*)&outv[4 * j];
}

// ============================================================================
// K5: link predictor.  blocks [0,B) -> pos (src,dst); [B,2B) -> neg (src,neg_dst)
// ============================================================================
__global__ __launch_bounds__(64) void k_link_pred(
    const int* __restrict__ src, const int* __restrict__ dst,
    const int* __restrict__ neg_dst,
    const float* __restrict__ lps_w, const float* __restrict__ lps_b,
    const float* __restrict__ lpd_w, const float* __restrict__ lpd_b,
    const float* __restrict__ lpf_w, const float* __restrict__ lpf_b,
    float* __restrict__ out, int Bn)
{
    __shared__ float sa[64], sb[64];
    __shared__ float red[2];
    int b = blockIdx.x;
    int t = threadIdx.x;
    int pos = (b < Bn);
    int bb = pos ? b : b - Bn;
    int sn = g_assoc[src[bb]];
    int dn = g_assoc[pos ? dst[bb] : neg_dst[bb]];
    sa[t] = g_h[(size_t)sn * 64 + t];
    sb[t] = g_h[(size_t)dn * 64 + t];
    __syncthreads();
    float hh = __ldg(lps_b + t) + __ldg(lpd_b + t);
#pragma unroll
    for (int d = 0; d < 64; d++)
        hh += sa[d] * __ldg(lps_w + d * 64 + t) + sb[d] * __ldg(lpd_w + d * 64 + t);
    hh = fmaxf(hh, 0.f);
    float p = hh * __ldg(lpf_w + t);
    p += __shfl_xor_sync(0xffffffffu, p, 16);
    p += __shfl_xor_sync(0xffffffffu, p, 8);
    p += __shfl_xor_sync(0xffffffffu, p, 4);
    p += __shfl_xor_sync(0xffffffffu, p, 2);
    p += __shfl_xor_sync(0xffffffffu, p, 1);
    if ((t & 31) == 0) red[t >> 5] = p;
    __syncthreads();
    if (t == 0) out[b] = red[0] + red[1] + __ldg(lpf_b);
}

// ============================================================================
extern "C" void kernel_launch(void* const* d_in, const int* in_sizes, int n_in,
                              void* d_out, int out_size)
{
    const float* memory      = (const float*)d_in[0];
    const float* pos_memory  = (const float*)d_in[1];
    const float* last_update = (const float*)d_in[2];
    const int*   n_id        = (const int*)  d_in[3];
    const int*   edge_index  = (const int*)  d_in[4];
    const float* edge_t      = (const float*)d_in[5];
    const float* edge_msg    = (const float*)d_in[6];
    const int*   src         = (const int*)  d_in[7];
    const int*   dst         = (const int*)  d_in[8];
    const int*   neg_dst     = (const int*)  d_in[9];
    const float* time_w      = (const float*)d_in[10];
    const float* time_b      = (const float*)d_in[11];
    const float* Wq          = (const float*)d_in[12];
    const float* bq          = (const float*)d_in[13];
    const float* Wk          = (const float*)d_in[14];
    const float* bk          = (const float*)d_in[15];
    const float* Wv          = (const float*)d_in[16];
    const float* bv          = (const float*)d_in[17];
    const float* We          = (const float*)d_in[18];
    const float* be          = (const float*)d_in[19];
    const float* Wskip       = (const float*)d_in[20];
    const float* bskip       = (const float*)d_in[21];
    const float* mlp_w       = (const float*)d_in[22];
    const float* mlp_b       = (const float*)d_in[23];
    const float* lps_w       = (const float*)d_in[24];
    const float* lps_b       = (const float*)d_in[25];
    const float* lpd_w       = (const float*)d_in[26];
    const float* lpd_b       = (const float*)d_in[27];
    const float* lpf_w       = (const float*)d_in[28];
    const float* lpf_b       = (const float*)d_in[29];

    int Nn       = in_sizes[3];   // 65536
    int numNodes = in_sizes[2];   // 100000
    int E        = in_sizes[5];   // 655360
    int Bn       = in_sizes[7];   // 4096
    float* out   = (float*)d_out;

    int initN = Nn * 128;
    k_init<<<(initN + 255) / 256, 256>>>(Nn, numNodes);
    k_scatter<<<(Nn + 255) / 256, 256>>>(n_id, last_update, Nn);
    k_mark<<<(3 * Bn + 255) / 256, 256>>>(src, dst, neg_dst, Bn);
    k_compact_nodes<<<(Nn + 255) / 256, 256>>>(Nn);
    k_compact_edges<<<(E + 255) / 256, 256>>>(edge_index, E);

    dim3 gg(4, (unsigned)(Nn >> 7));
    k_node_gemm<<<gg, 256>>>(n_id, memory, pos_memory,
                             Wq, Wk, Wv, Wskip, bq, bk, bv, bskip);

    k_edge<<<(E + 127) / 128, 256>>>(edge_index, edge_t, edge_msg,
                                     We, be, time_w, time_b, E);

    k_node_final<<<(Nn + 63) / 64, 256>>>(mlp_w, mlp_b);

    k_link_pred<<<2 * Bn, 64>>>(src, dst, neg_dst,
                                lps_w, lps_b, lpd_w, lpd_b, lpf_w, lpf_b,
                                out, Bn);
}